// round 17
// baseline (speedup 1.0000x reference)
#include <cuda_runtime.h>
#include <cstdint>

#define ALPHA 0.2f

// ---------------- static scratch (allocation-free) ----------------
__device__ uint32_t g_Whh[8 * 4 * 32 * 1024];   // 4MB fp16x2: [bh][n][jpair]
__device__ uint32_t g_esea16[8 * 4 * 2048];     // fp16x2 (es, ea) per node
__device__ uint32_t g_sedb[8 * 4 * 2048];       // pairs: (ed2(c), eb2(c)) u32 stream
__device__ uint32_t g_adjb[8 * 64 * 2048];      // 4MB bitmask, rows permuted g*4+r

__device__ __forceinline__ uint32_t pack_h2(float lo, float hi) {
    uint32_t d;
    asm("cvt.rn.f16x2.f32 %0, %1, %2;" : "=r"(d) : "f"(hi), "f"(lo));
    return d;
}
__device__ __forceinline__ uint32_t prmt(uint32_t a, uint32_t b, uint32_t s) {
    uint32_t d;
    asm("prmt.b32 %0, %1, %2, %3;" : "=r"(d) : "r"(a), "r"(b), "r"(s));
    return d;
}
__device__ __forceinline__ uint32_t hmul2(uint32_t a, uint32_t b) {
    uint32_t d;
    asm("mul.f16x2 %0, %1, %2;" : "=r"(d) : "r"(a), "r"(b));
    return d;
}
__device__ __forceinline__ uint32_t hmax2(uint32_t a, uint32_t b) {
    uint32_t d;
    asm("max.f16x2 %0, %1, %2;" : "=r"(d) : "r"(a), "r"(b));
    return d;
}
__device__ __forceinline__ uint32_t smem_u32(const void* p) {
    uint32_t a;
    asm("{ .reg .u64 t; cvta.to.shared.u64 t, %1; cvt.u32.u64 %0, t; }"
        : "=r"(a) : "l"(p));
    return a;
}
__device__ __forceinline__ void mma16816(float* d, const uint32_t* a,
                                         const uint32_t* b) {
    asm volatile(
        "mma.sync.aligned.m16n8k16.row.col.f32.f16.f16.f32 "
        "{%0,%1,%2,%3}, {%4,%5,%6,%7}, {%8,%9}, {%0,%1,%2,%3};"
        : "+f"(d[0]), "+f"(d[1]), "+f"(d[2]), "+f"(d[3])
        : "r"(a[0]), "r"(a[1]), "r"(a[2]), "r"(a[3]), "r"(b[0]), "r"(b[1]));
}
__device__ __forceinline__ void ldmx4(uint32_t* r, uint32_t addr) {
    asm volatile("ldmatrix.sync.aligned.m8n8.x4.shared.b16 {%0,%1,%2,%3}, [%4];"
                 : "=r"(r[0]), "=r"(r[1]), "=r"(r[2]), "=r"(r[3]) : "r"(addr));
}
__device__ __forceinline__ void cpa16(uint32_t dst, const void* src) {
    asm volatile("cp.async.cg.shared.global [%0], [%1], 16;"
                 :: "r"(dst), "l"(src) : "memory");
}
#define CPA_COMMIT() asm volatile("cp.async.commit_group;" ::: "memory")
#define CPA_WAIT0()  asm volatile("cp.async.wait_group 0;" ::: "memory")

// ---------------------------------------------------------------------------
// Kernel 0 (fused pre-pass, parity-interleaved): even CTAs bitpack adj
// (adj values are {0,1} -> arithmetic nibble build; permuted row store
// g*4+r); odd CTAs projection GEMM (W chunked) + factorized exps.
// ---------------------------------------------------------------------------
__global__ __launch_bounds__(256) void k_pre(const int* __restrict__ adj,
                                             const float* __restrict__ h,
                                             const float* __restrict__ W,
                                             const float* __restrict__ a) {
    extern __shared__ __align__(16) char sm[];
    int tid = threadIdx.x;
    int cid = blockIdx.x >> 1;

    if (!(blockIdx.x & 1)) {
        // ---------------- bitpack body ----------------
        uint32_t* sw = (uint32_t*)sm;                 // 2048 u32
        int b = cid >> 6, i0 = (cid & 63) * 32;
        int lane = tid & 31, w = tid >> 5;
        uint32_t oct = (uint32_t)(lane & 7) * 4u;
#pragma unroll
        for (int r = 0; r < 4; r++) {
            int ii = w * 4 + r;
            const int4* ap = (const int4*)(adj + ((size_t)(b * 2048 + i0 + ii)) * 2048) + lane;
#pragma unroll 8
            for (int c = 0; c < 16; c++) {
                int4 v = __ldcs(ap + (size_t)c * 32);
                // adj in {0,1}: nibble by shifted OR (2 LOP3 on SASS)
                uint32_t nib = (uint32_t)v.x | ((uint32_t)v.y << 1) |
                               ((uint32_t)v.z << 2) | ((uint32_t)v.w << 3);
                uint32_t word = nib << oct;
                word |= __shfl_xor_sync(0xffffffffu, word, 1);
                word |= __shfl_xor_sync(0xffffffffu, word, 2);
                word |= __shfl_xor_sync(0xffffffffu, word, 4);
                if ((lane & 7) == 0)
                    sw[(c * 4 + (lane >> 3)) * 32 + ii] = word;
            }
        }
        __syncthreads();
        for (int idx = tid; idx < 2048; idx += 256) {
            int wd = idx >> 5, ii = idx & 31;
            int pp = ((ii & 7) << 2) | (ii >> 3);   // permuted: g*4 + r
            g_adjb[((size_t)(b * 64 + wd)) * 2048 + i0 + pp] = sw[idx];
        }
        return;
    }

    // ---------------- projection body (W chunked: 16x128 per step) --------
    float* Ws = (float*)sm;                           // 8KB chunk
    char* pool = sm + 8192;
    float* aS = (float*)(sm + 8192 + 8704);
    float* aD = aS + 128;
    float* hs = (float*)pool;
    uint32_t* T = (uint32_t*)pool;

    int b = cid >> 6, n0 = (cid & 63) * 32;

    const float* hp = h + ((size_t)(b * 2048 + n0)) * 64;
    for (int i = tid; i < 32 * 64 / 4; i += 256)
        ((float4*)hs)[i] = ((const float4*)hp)[i];
    if (tid < 128) {
        aS[tid] = a[(tid >> 5) * 64 + (tid & 31)];
        aD[tid] = a[(tid >> 5) * 64 + 32 + (tid & 31)];
    }

    int tx = tid & 31, ty = tid >> 5;
    int r0 = ty * 4, c0 = tx * 4;
    float acc[4][4] = {};
#pragma unroll
    for (int kc = 0; kc < 4; kc++) {
        __syncthreads();
        for (int i = tid; i < 16 * 128 / 4; i += 256)
            ((float4*)Ws)[i] = ((const float4*)W)[kc * (16 * 128 / 4) + i];
        __syncthreads();
#pragma unroll
        for (int k = 0; k < 16; k++) {
            float4 wv = *(float4*)&Ws[k * 128 + c0];
#pragma unroll
            for (int r = 0; r < 4; r++) {
                float hv = hs[(r0 + r) * 64 + kc * 16 + k];
                acc[r][0] += hv * wv.x; acc[r][1] += hv * wv.y;
                acc[r][2] += hv * wv.z; acc[r][3] += hv * wv.w;
            }
        }
    }

    float4 as4 = *(float4*)&aS[c0];
    float4 ad4 = *(float4*)&aD[c0];
    float sr[4], dr[4];
#pragma unroll
    for (int r = 0; r < 4; r++) {
        sr[r] = acc[r][0] * as4.x + acc[r][1] * as4.y +
                acc[r][2] * as4.z + acc[r][3] * as4.w;
        dr[r] = acc[r][0] * ad4.x + acc[r][1] * ad4.y +
                acc[r][2] * ad4.z + acc[r][3] * ad4.w;
    }
#pragma unroll
    for (int o = 4; o > 0; o >>= 1) {
#pragma unroll
        for (int r = 0; r < 4; r++) {
            sr[r] += __shfl_xor_sync(0xffffffffu, sr[r], o);
            dr[r] += __shfl_xor_sync(0xffffffffu, dr[r], o);
        }
    }
    if ((tx & 7) == 0) {
        int hh = tx >> 3;
        int base = (b * 4 + hh) * 2048 + n0 + r0;
#pragma unroll
        for (int r = 0; r < 4; r++)
            g_esea16[base + r] = pack_h2(expf(sr[r]), expf(ALPHA * sr[r]));
        uint4 sv;
        sv.x = pack_h2(expf(dr[0]), expf(dr[1]));
        sv.y = pack_h2(expf(ALPHA * dr[0]), expf(ALPHA * dr[1]));
        sv.z = pack_h2(expf(dr[2]), expf(dr[3]));
        sv.w = pack_h2(expf(ALPHA * dr[2]), expf(ALPHA * dr[3]));
        *(uint4*)&g_sedb[base] = sv;
    }

    __syncthreads();
#pragma unroll
    for (int c = 0; c < 4; c++) {
        T[(c0 + c) * 17 + ty * 2]     = pack_h2(acc[0][c], acc[1][c]);
        T[(c0 + c) * 17 + ty * 2 + 1] = pack_h2(acc[2][c], acc[3][c]);
    }
    __syncthreads();
    {
        int ch = tid >> 1, q = (tid & 1) * 8;
        int hh = ch >> 5, n = ch & 31;
        uint32_t* gp = &g_Whh[((size_t)((b * 4 + hh) * 32 + n)) * 1024 + (n0 >> 1) + q];
        uint32_t v[8];
#pragma unroll
        for (int i = 0; i < 8; i++) v[i] = T[ch * 17 + q + i];
        *(uint4*)gp = make_uint4(v[0], v[1], v[2], v[3]);
        *(uint4*)(gp + 4) = make_uint4(v[4], v[5], v[6], v[7]);
    }
}

// ---------------------------------------------------------------------------
// Kernel 1: attention — 32 i-rows/warp, A-fragments in registers, cp.async
// staging. Rowsum B-fragment is a per-thread CONSTANT (g==0 -> (1h,1h)),
// so B smem holds only the 32 Wh rows and the ldmx2 is gone.
// ---------------------------------------------------------------------------
#define PST 68
#define BBUF 2176                    // 32 * PST
#define OFF_B  0
#define OFF_BT (2 * BBUF)            // 4352: bits, 2 x 1024 (4 wd x 256 perm)
#define OFF_SD (OFF_BT + 2 * 1024)   // 6400: sed stream, 2 x 128
#define OFF_LT (OFF_SD + 2 * 128)    // 6656
#define SMEM_W (OFF_LT + 8)          // 6664 u32 = 26656 B

__global__ __launch_bounds__(256, 2) void k_attn(float* __restrict__ out) {
    extern __shared__ uint32_t smu[];
    uint32_t* slut = smu + OFF_LT;
    uint32_t sb = smem_u32(smu);

    int tid = threadIdx.x, lane = tid & 31, wid = tid >> 5;
    int b = blockIdx.z, hh = blockIdx.y, i0 = blockIdx.x * 256;
    int bh = (b * 4 + hh) * 2048;
    int bh4 = b * 4 + hh;
    int g = lane >> 2, tg = lane & 3;
    int m0 = wid * 32;
    int tsh = 2 * tg;

    if (tid < 4)
        slut[tid] = ((tid & 1) ? 0x0000FFFFu : 0u) | ((tid & 2) ? 0xFFFF0000u : 0u);

    // rowsum B-fragment: constant (n = g == 0 column of the ones tile)
    uint32_t b4[2];
    b4[0] = b4[1] = (g == 0) ? 0x3C003C00u : 0u;

    // per-thread row constants: 4 rows (m0+g, +8, +16, +24)
    uint32_t es2[4], ea2[4];
#pragma unroll
    for (int r = 0; r < 4; r++) {
        uint32_t ee = g_esea16[bh + i0 + m0 + r * 8 + g];
        es2[r] = prmt(ee, ee, 0x1010);
        ea2[r] = prmt(ee, ee, 0x3232);
    }

    // ldmatrix B lane addresses (buffer 0, bytes)
    uint32_t aB01 = sb + 4u * (OFF_B +
        (uint32_t)(((lane & 7) + ((lane >> 4) & 1) * 8) * PST) +
        (uint32_t)(((lane >> 3) & 1) * 4));
    uint32_t aB23 = aB01 + 4u * 16 * PST;

    float d[2][5][4] = {};

    int s_wd = tid >> 6, s_m = (tid & 63) * 4;

    auto stage = [&](int t) {
        int buf = t & 1;
        cpa16(sb + 4u * (uint32_t)(OFF_BT + buf * 1024 + s_wd * 256 + s_m),
              &g_adjb[((size_t)(b * 64 + t * 4 + s_wd)) * 2048 + i0 + s_m]);
        int j0h = t * 64;
#pragma unroll
        for (int p = 0; p < 2; p++) {
            int c = tid + p * 256;
            int n = c >> 4, ch16 = c & 15;
            cpa16(sb + 4u * (uint32_t)(OFF_B + buf * BBUF + n * PST + ch16 * 4),
                  &g_Whh[((size_t)(bh4 * 32 + n)) * 1024 + j0h + ch16 * 4]);
        }
        if (tid < 32)
            cpa16(sb + 4u * (uint32_t)(OFF_SD + buf * 128 + tid * 4),
                  &g_sedb[bh4 * 2048 + t * 128 + tid * 4]);
        CPA_COMMIT();
    };

    stage(0);

    for (int t = 0; t < 16; t++) {
        CPA_WAIT0();
        __syncthreads();
        if (t < 15) stage(t + 1);

        int buf = t & 1;
        uint32_t* sbT = smu + OFF_BT + buf * 1024;
        uint32_t* sd  = smu + OFF_SD + buf * 128;
        uint32_t bofs = (uint32_t)buf * (BBUF * 4u);

        // bit words: 4 LDS.128 (components r=0..3)
        uint4 wr4[4];
#pragma unroll
        for (int wd = 0; wd < 4; wd++)
            wr4[wd] = *(const uint4*)&sbT[wd * 256 + m0 + g * 4];

#pragma unroll
        for (int kk = 0; kk < 8; kk++) {
            uint32_t sh16 = (uint32_t)((kk & 1) * 16);
            uint2 eA = *(const uint2*)&sd[2 * (kk * 8 + tg)];
            uint2 eB = *(const uint2*)&sd[2 * (kk * 8 + 4 + tg)];
            const uint32_t* wrp = (const uint32_t*)&wr4[kk >> 1];
            uint32_t a0[4], a1[4];
#pragma unroll
            for (int s = 0; s < 2; s++) {
                uint32_t* ar = s ? a1 : a0;
                int rl = s * 2, rh = s * 2 + 1;
                uint32_t wl = wrp[rl] >> sh16;
                uint32_t wh = wrp[rh] >> sh16;
                ar[0] = hmax2(hmul2(es2[rl], eA.x), hmul2(ea2[rl], eA.y)) &
                        slut[(wl >> tsh) & 3];
                ar[1] = hmax2(hmul2(es2[rh], eA.x), hmul2(ea2[rh], eA.y)) &
                        slut[(wh >> tsh) & 3];
                ar[2] = hmax2(hmul2(es2[rl], eB.x), hmul2(ea2[rl], eB.y)) &
                        slut[(wl >> (tsh + 8)) & 3];
                ar[3] = hmax2(hmul2(es2[rh], eB.x), hmul2(ea2[rh], eB.y)) &
                        slut[(wh >> (tsh + 8)) & 3];
            }

            uint32_t kb = bofs + (uint32_t)kk * 32;
            uint32_t b01[4], b23[4];
            ldmx4(b01, aB01 + kb);
            ldmx4(b23, aB23 + kb);
            mma16816(d[0][0], a0, &b01[0]); mma16816(d[0][1], a0, &b01[2]);
            mma16816(d[0][2], a0, &b23[0]); mma16816(d[0][3], a0, &b23[2]);
            mma16816(d[0][4], a0, b4);
            mma16816(d[1][0], a1, &b01[0]); mma16816(d[1][1], a1, &b01[2]);
            mma16816(d[1][2], a1, &b23[0]); mma16816(d[1][3], a1, &b23[2]);
            mma16816(d[1][4], a1, b4);
        }
    }

    // epilogue: per set, rowsum = D[:,32]; broadcast + divide
#pragma unroll
    for (int s = 0; s < 2; s++) {
        float rs_lo = __shfl_sync(0xffffffffu, d[s][4][0], lane & ~3);
        float rs_hi = __shfl_sync(0xffffffffu, d[s][4][2], lane & ~3);
        float inv_lo = 1.0f / rs_lo, inv_hi = 1.0f / rs_hi;
        size_t row_lo = (size_t)(b * 2048 + i0 + m0 + s * 16 + g);
        size_t row_hi = row_lo + 8;
        int cb = hh * 32;
#pragma unroll
        for (int n = 0; n < 4; n++) {
            int c = cb + n * 8 + 2 * tg;
            *(float2*)&out[row_lo * 128 + c] =
                make_float2(d[s][n][0] * inv_lo, d[s][n][1] * inv_lo);
            *(float2*)&out[row_hi * 128 + c] =
                make_float2(d[s][n][2] * inv_hi, d[s][n][3] * inv_hi);
        }
    }
}

// ---------------------------------------------------------------------------
extern "C" void kernel_launch(void* const* d_in, const int* in_sizes, int n_in,
                              void* d_out, int out_size) {
    const float* h   = (const float*)d_in[0];
    const int*   adj = (const int*)d_in[1];
    const float* W   = (const float*)d_in[2];
    const float* a   = (const float*)d_in[3];
    float* out = (float*)d_out;

    int pre_smem = 17920;   // max(pack 8KB, proj ~17.6KB)
    k_pre<<<1024, 256, pre_smem>>>(adj, h, W, a);

    int smem_bytes = SMEM_W * (int)sizeof(uint32_t);   // ~26.7KB
    cudaFuncSetAttribute(k_attn, cudaFuncAttributeMaxDynamicSharedMemorySize,
                         smem_bytes);
    k_attn<<<dim3(8, 4, 8), 256, smem_bytes>>>(out);
}